// round 2
// baseline (speedup 1.0000x reference)
#include <cuda_runtime.h>

// RNN: h_t = tanh([x_t, h_{t-1}] @ W_cell + b_cell), logits = h_T @ W_out + b_out
// B=4096, T=128, D=128, H=150, O=10.
//
// Persistent-CTA + packed fp32 FFMA2 (fma.rn.f32x2) inner loop.
// Each CTA owns 32 batch rows for all 128 steps. 160 threads, per-thread tile
// 8 batch x 4 hidden. Accumulators are 64-bit packed fp32 pairs over batch.

#define T_SEQ   128
#define D_IN    128
#define H_HID   150
#define O_OUT   10
#define KDIM    (D_IN + H_HID)   // 278
#define JPAD    160              // 40 j-groups * 4
#define B_BLK   32
#define APAD    36
#define NTHREADS 160             // 40 jg * 4 bg(8 rows)

typedef unsigned long long ull;

__device__ __forceinline__ ull fma2(ull a, ull b, ull c) {
    ull d;
    asm("fma.rn.f32x2 %0, %1, %2, %3;" : "=l"(d) : "l"(a), "l"(b), "l"(c));
    return d;
}
__device__ __forceinline__ ull packdup(float w) {
    ull d;
    asm("mov.b64 %0, {%1, %2};" : "=l"(d) : "f"(w), "f"(w));
    return d;
}
__device__ __forceinline__ void unpack2(ull v, float& lo, float& hi) {
    asm("mov.b64 {%0, %1}, %2;" : "=f"(lo), "=f"(hi) : "l"(v));
}

__global__ void __launch_bounds__(NTHREADS, 1)
rnn_ffma2_kernel(const float* __restrict__ X,
                 const float* __restrict__ Wc,
                 const float* __restrict__ bc,
                 const float* __restrict__ Wo,
                 const float* __restrict__ bo,
                 float* __restrict__ out)
{
    extern __shared__ float smem[];
    float* Wsh = smem;                                // [KDIM][JPAD]
    float* Ash = Wsh + KDIM * JPAD;                   // [(D_IN+JPAD)][APAD]
    float* bsh = Ash + (D_IN + JPAD) * APAD;          // [JPAD]

    const int tid = threadIdx.x;
    const long ctaB0 = (long)blockIdx.x * B_BLK;
    const float* Xb = X + ctaB0 * T_SEQ * D_IN;

    // ---- one-time loads ----
    for (int i = tid; i < KDIM * JPAD; i += NTHREADS) {
        int k = i / JPAD;
        int j = i - k * JPAD;
        Wsh[i] = (j < H_HID) ? Wc[k * H_HID + j] : 0.0f;
    }
    for (int j = tid; j < JPAD; j += NTHREADS)
        bsh[j] = (j < H_HID) ? bc[j] : 0.0f;
    for (int i = tid; i < JPAD * APAD; i += NTHREADS)
        Ash[D_IN * APAD + i] = 0.0f;

    // x_0 transposed into A[0..127][b]
#pragma unroll
    for (int s = 0; s < 7; s++) {
        int i = tid + s * NTHREADS;
        if (i < B_BLK * (D_IN / 4)) {       // 1024 float4s
            int r = i >> 5;
            int c = i & 31;
            float4 v = *(const float4*)&Xb[(long)r * T_SEQ * D_IN + c * 4];
            Ash[(c * 4 + 0) * APAD + r] = v.x;
            Ash[(c * 4 + 1) * APAD + r] = v.y;
            Ash[(c * 4 + 2) * APAD + r] = v.z;
            Ash[(c * 4 + 3) * APAD + r] = v.w;
        }
    }
    __syncthreads();

    const int jg = tid % 40;
    const int bg = tid / 40;        // 0..3, 8 batch rows each
    const int j0 = jg * 4;
    const int b0 = bg * 8;
    const float4 bias = *(const float4*)&bsh[j0];

    for (int t = 0; t < T_SEQ; t++) {
        // prefetch x_{t+1}
        float4 xr[7];
        const bool havex = (t + 1 < T_SEQ);
        if (havex) {
#pragma unroll
            for (int s = 0; s < 7; s++) {
                int i = tid + s * NTHREADS;
                if (i < B_BLK * (D_IN / 4)) {
                    int r = i >> 5;
                    int c = i & 31;
                    xr[s] = *(const float4*)&Xb[(long)r * T_SEQ * D_IN + (long)(t + 1) * D_IN + c * 4];
                }
            }
        }

        // ---- packed GEMM tile: acc[j][bp] (+= a-pair * (w_j,w_j)) ----
        ull acc[4][4];
#pragma unroll
        for (int j = 0; j < 4; j++)
#pragma unroll
            for (int p = 0; p < 4; p++)
                acc[j][p] = 0ULL;

#pragma unroll 2
        for (int k = 0; k < KDIM; k++) {
            float4 wv = *(const float4*)&Wsh[k * JPAD + j0];
            ull w0 = packdup(wv.x), w1 = packdup(wv.y);
            ull w2 = packdup(wv.z), w3 = packdup(wv.w);
            ulonglong2 aA = *(const ulonglong2*)&Ash[k * APAD + b0];      // (a0,a1),(a2,a3)
            ulonglong2 aB = *(const ulonglong2*)&Ash[k * APAD + b0 + 4];  // (a4,a5),(a6,a7)
            acc[0][0] = fma2(aA.x, w0, acc[0][0]);
            acc[0][1] = fma2(aA.y, w0, acc[0][1]);
            acc[0][2] = fma2(aB.x, w0, acc[0][2]);
            acc[0][3] = fma2(aB.y, w0, acc[0][3]);
            acc[1][0] = fma2(aA.x, w1, acc[1][0]);
            acc[1][1] = fma2(aA.y, w1, acc[1][1]);
            acc[1][2] = fma2(aB.x, w1, acc[1][2]);
            acc[1][3] = fma2(aB.y, w1, acc[1][3]);
            acc[2][0] = fma2(aA.x, w2, acc[2][0]);
            acc[2][1] = fma2(aA.y, w2, acc[2][1]);
            acc[2][2] = fma2(aB.x, w2, acc[2][2]);
            acc[2][3] = fma2(aB.y, w2, acc[2][3]);
            acc[3][0] = fma2(aA.x, w3, acc[3][0]);
            acc[3][1] = fma2(aA.y, w3, acc[3][1]);
            acc[3][2] = fma2(aB.x, w3, acc[3][2]);
            acc[3][3] = fma2(aB.y, w3, acc[3][3]);
        }

        __syncthreads();   // all reads of A done

        // h_new = tanh(acc + bias)  -> A rows D_IN+j, vectorized over batch
        const float bj[4] = {bias.x, bias.y, bias.z, bias.w};
#pragma unroll
        for (int j = 0; j < 4; j++) {
            float h[8];
#pragma unroll
            for (int p = 0; p < 4; p++) {
                float lo, hi;
                unpack2(acc[j][p], lo, hi);
                h[2 * p]     = tanhf(lo + bj[j]);
                h[2 * p + 1] = tanhf(hi + bj[j]);
            }
            *(float4*)&Ash[(D_IN + j0 + j) * APAD + b0]     = make_float4(h[0], h[1], h[2], h[3]);
            *(float4*)&Ash[(D_IN + j0 + j) * APAD + b0 + 4] = make_float4(h[4], h[5], h[6], h[7]);
        }

        // store prefetched x_{t+1} transposed
        if (havex) {
#pragma unroll
            for (int s = 0; s < 7; s++) {
                int i = tid + s * NTHREADS;
                if (i < B_BLK * (D_IN / 4)) {
                    int r = i >> 5;
                    int c = i & 31;
                    Ash[(c * 4 + 0) * APAD + r] = xr[s].x;
                    Ash[(c * 4 + 1) * APAD + r] = xr[s].y;
                    Ash[(c * 4 + 2) * APAD + r] = xr[s].z;
                    Ash[(c * 4 + 3) * APAD + r] = xr[s].w;
                }
            }
        }
        __syncthreads();
    }

    // ---- classifier head: 320 (b,o) pairs over 160 threads ----
#pragma unroll
    for (int s = 0; s < 2; s++) {
        int i = tid + s * NTHREADS;
        const int b = i / O_OUT;
        const int o = i - b * O_OUT;
        float sum = bo[o];
#pragma unroll 5
        for (int j = 0; j < H_HID; j++)
            sum += Ash[(D_IN + j) * APAD + b] * Wo[j * O_OUT + o];
        out[(ctaB0 + b) * O_OUT + o] = sum;
    }
}

extern "C" void kernel_launch(void* const* d_in, const int* in_sizes, int n_in,
                              void* d_out, int out_size)
{
    const float* X  = (const float*)d_in[0];
    const float* Wc = (const float*)d_in[1];
    const float* bc = (const float*)d_in[2];
    const float* Wo = (const float*)d_in[3];
    const float* bo = (const float*)d_in[4];
    float* out = (float*)d_out;

    const int B = in_sizes[0] / (T_SEQ * D_IN);
    const size_t smem_bytes =
        (size_t)(KDIM * JPAD + (D_IN + JPAD) * APAD + JPAD) * sizeof(float);

    cudaFuncSetAttribute(rnn_ffma2_kernel,
                         cudaFuncAttributeMaxDynamicSharedMemorySize,
                         (int)smem_bytes);

    rnn_ffma2_kernel<<<B / B_BLK, NTHREADS, smem_bytes>>>(X, Wc, bc, Wo, bo, out);
}